// round 8
// baseline (speedup 1.0000x reference)
#include <cuda_runtime.h>
#include <cuda_bf16.h>

#define N_NODES 50000
#define N_EDGES 800000
#define FEAT 10
#define HID 64
#define N_SHEETS 256
#define SHEET_LEN 128

#define SCAN_BLK 512
#define SCAN_GRID ((N_NODES + SCAN_BLK - 1) / SCAN_BLK)   // 98

#define NPB 64          // nodes per block in fused layer kernel
#define LAYER_THREADS 256

// ---------------- scratch (static device globals; no allocation) ----------------
__device__ float d_hA[N_NODES * HID];
__device__ float d_hB[N_NODES * HID];
__device__ int   d_deg[N_NODES];
__device__ float d_dinv[N_NODES];
__device__ int   d_rowptr[N_NODES + 1];
__device__ int   d_rowcur[N_NODES];
__device__ int   d_csrsrc[N_EDGES];
__device__ int   d_part[SCAN_GRID + 32];
__device__ float d_gsum[HID];

// ---------------- CSR build ----------------

__global__ void zero_kernel(int* deg, float* gsum, int n) {
    int i = blockIdx.x * blockDim.x + threadIdx.x;
    if (i < n) deg[i] = 0;
    if (i < HID) gsum[i] = 0.f;
}

__global__ void deg_kernel(const int* __restrict__ dst, int* __restrict__ deg, int nE) {
    int e = blockIdx.x * blockDim.x + threadIdx.x;
    if (e < nE) atomicAdd(&deg[dst[e]], 1);
}

// pass 1: per-block sums of deg, plus dinv (reads deg anyway)
__global__ void scan1_kernel(const int* __restrict__ deg, float* __restrict__ dinv,
                             int* __restrict__ partials, int n) {
    __shared__ int ws[SCAN_BLK / 32];
    int i = blockIdx.x * blockDim.x + threadIdx.x;
    int lane = threadIdx.x & 31, wrp = threadIdx.x >> 5;
    int v = (i < n) ? deg[i] : 0;
    if (i < n) dinv[i] = rsqrtf((float)v + 1.0f);
    int s = v;
    #pragma unroll
    for (int off = 16; off; off >>= 1) s += __shfl_down_sync(0xffffffffu, s, off);
    if (lane == 0) ws[wrp] = s;
    __syncthreads();
    if (wrp == 0) {
        int t = (lane < SCAN_BLK / 32) ? ws[lane] : 0;
        #pragma unroll
        for (int off = 16; off; off >>= 1) t += __shfl_down_sync(0xffffffffu, t, off);
        if (lane == 0) partials[blockIdx.x] = t;
    }
}

// pass 2: exclusive scan of the 98 block partials
__global__ void scan2_kernel(int* __restrict__ partials, int nb, int* __restrict__ total_dst) {
    __shared__ int ws[4];
    int t = threadIdx.x;
    int lane = t & 31, wrp = t >> 5;
    int v = (t < nb) ? partials[t] : 0;
    int x = v;
    #pragma unroll
    for (int off = 1; off < 32; off <<= 1) {
        int y = __shfl_up_sync(0xffffffffu, x, off);
        if (lane >= off) x += y;
    }
    if (lane == 31) ws[wrp] = x;
    __syncthreads();
    if (wrp == 0 && lane < 4) {
        int y = ws[lane];
        #pragma unroll
        for (int off = 1; off < 4; off <<= 1) {
            int z = __shfl_up_sync(0x0000000fu, y, off);
            if (lane >= off) y += z;
        }
        ws[lane] = y;
    }
    __syncthreads();
    int incl = x + (wrp > 0 ? ws[wrp - 1] : 0);
    if (t < nb) partials[t] = incl - v;
    if (t == 127) *total_dst = incl;
}

// pass 3: per-block rescan + offset -> rowptr/rowcur
__global__ void scan3_kernel(const int* __restrict__ deg, const int* __restrict__ partials,
                             int* __restrict__ row_ptr, int* __restrict__ row_cur, int n) {
    __shared__ int ws[SCAN_BLK / 32];
    int i = blockIdx.x * blockDim.x + threadIdx.x;
    int lane = threadIdx.x & 31, wrp = threadIdx.x >> 5;
    int v = (i < n) ? deg[i] : 0;
    int x = v;
    #pragma unroll
    for (int off = 1; off < 32; off <<= 1) {
        int y = __shfl_up_sync(0xffffffffu, x, off);
        if (lane >= off) x += y;
    }
    if (lane == 31) ws[wrp] = x;
    __syncthreads();
    if (wrp == 0) {
        int y = (lane < SCAN_BLK / 32) ? ws[lane] : 0;
        #pragma unroll
        for (int off = 1; off < 16; off <<= 1) {
            int z = __shfl_up_sync(0xffffffffu, y, off);
            if (lane >= off) y += z;
        }
        if (lane < SCAN_BLK / 32) ws[lane] = y;
    }
    __syncthreads();
    int excl = x - v + (wrp > 0 ? ws[wrp - 1] : 0) + partials[blockIdx.x];
    if (i < n) { row_ptr[i] = excl; row_cur[i] = excl; }
}

__global__ void scatter_kernel(const int* __restrict__ src, const int* __restrict__ dst,
                               int* __restrict__ rowcur, int* __restrict__ csrsrc, int nE) {
    int e = blockIdx.x * blockDim.x + threadIdx.x;
    if (e >= nE) return;
    int d = dst[e];
    int p = atomicAdd(&rowcur[d], 1);
    csrsrc[p] = src[e];
}

// ---------------- fused layer: out = relu(agg(Hprev) @ W + b) ----------------
// Phase A: warp-per-node CSR gather of Hprev (K-wide) -> smem
// Phase B: 4 threads/node x 16 outputs: smem X @ smem W, bias+relu, coalesced store.
template <int K>
__global__ void __launch_bounds__(LAYER_THREADS)
layer_kernel(const float* __restrict__ Hprev, const int* __restrict__ row_ptr,
             const int* __restrict__ csrsrc, const float* __restrict__ dinv,
             const float* __restrict__ W, const float* __restrict__ b,
             float* __restrict__ Hout, int n) {
    __shared__ __align__(16) float Wsm[K * HID];
    __shared__ float bsm[HID];
    __shared__ float Xsm[NPB * (K + 1)];    // +1 pad: conflict-free phase-B reads

    const int tid  = threadIdx.x;
    const int lane = tid & 31;
    const int wrp  = tid >> 5;
    const int base = blockIdx.x * NPB;

    for (int i = tid; i < K * HID; i += LAYER_THREADS) Wsm[i] = W[i];
    if (tid < HID) bsm[tid] = b[tid];

    // ---- Phase A: aggregation (linear; bias/relu deferred to after GEMM) ----
    #pragma unroll
    for (int i = 0; i < NPB / (LAYER_THREADS / 32); i++) {
        int nl = wrp * (NPB / (LAYER_THREADS / 32)) + i;   // 0..NPB-1
        int node = base + nl;
        if (node < n) {
            int beg = row_ptr[node];
            int end = row_ptr[node + 1];
            if (K == HID) {
                float a0 = 0.f, a1 = 0.f;
                for (int e = beg; e < end; e++) {
                    int s = csrsrc[e];                 // warp-uniform
                    float w = dinv[s];                 // warp-uniform
                    a0 = fmaf(w, Hprev[(size_t)s * HID + lane], a0);
                    a1 = fmaf(w, Hprev[(size_t)s * HID + 32 + lane], a1);
                }
                float di = dinv[node];
                a0 = di * fmaf(Hprev[(size_t)node * HID + lane],      di, a0);
                a1 = di * fmaf(Hprev[(size_t)node * HID + 32 + lane], di, a1);
                Xsm[nl * (K + 1) + lane]      = a0;
                Xsm[nl * (K + 1) + 32 + lane] = a1;
            } else {
                float a0 = 0.f;
                for (int e = beg; e < end; e++) {
                    int s = csrsrc[e];
                    float w = dinv[s];
                    if (lane < K)
                        a0 = fmaf(w, Hprev[(size_t)s * K + lane], a0);
                }
                if (lane < K) {
                    float di = dinv[node];
                    Xsm[nl * (K + 1) + lane] =
                        di * fmaf(Hprev[(size_t)node * K + lane], di, a0);
                }
            }
        }
    }
    __syncthreads();

    // ---- Phase B: GEMM + bias + relu ----
    const int nl = tid >> 2;            // 0..63
    const int q  = tid & 3;             // output group q*16 .. q*16+15
    const int node = base + nl;
    float acc[16];
    #pragma unroll
    for (int j = 0; j < 16; j++) acc[j] = 0.f;

    #pragma unroll 8
    for (int k = 0; k < K; k++) {
        float xv = Xsm[nl * (K + 1) + k];
        const float4* wr = (const float4*)&Wsm[k * HID + q * 16];
        float4 w0 = wr[0], w1 = wr[1], w2 = wr[2], w3 = wr[3];
        acc[0]  = fmaf(xv, w0.x, acc[0]);  acc[1]  = fmaf(xv, w0.y, acc[1]);
        acc[2]  = fmaf(xv, w0.z, acc[2]);  acc[3]  = fmaf(xv, w0.w, acc[3]);
        acc[4]  = fmaf(xv, w1.x, acc[4]);  acc[5]  = fmaf(xv, w1.y, acc[5]);
        acc[6]  = fmaf(xv, w1.z, acc[6]);  acc[7]  = fmaf(xv, w1.w, acc[7]);
        acc[8]  = fmaf(xv, w2.x, acc[8]);  acc[9]  = fmaf(xv, w2.y, acc[9]);
        acc[10] = fmaf(xv, w2.z, acc[10]); acc[11] = fmaf(xv, w2.w, acc[11]);
        acc[12] = fmaf(xv, w3.x, acc[12]); acc[13] = fmaf(xv, w3.y, acc[13]);
        acc[14] = fmaf(xv, w3.z, acc[14]); acc[15] = fmaf(xv, w3.w, acc[15]);
    }

    if (node < n) {
        float4* orow = (float4*)(Hout + (size_t)node * HID + q * 16);
        #pragma unroll
        for (int jj = 0; jj < 4; jj++) {
            float4 v;
            v.x = fmaxf(acc[4*jj+0] + bsm[q*16 + 4*jj+0], 0.f);
            v.y = fmaxf(acc[4*jj+1] + bsm[q*16 + 4*jj+1], 0.f);
            v.z = fmaxf(acc[4*jj+2] + bsm[q*16 + 4*jj+2], 0.f);
            v.w = fmaxf(acc[4*jj+3] + bsm[q*16 + 4*jj+3], 0.f);
            orow[jj] = v;
        }
    }
}

// ---------------- pooling + tail ----------------

// grid-stride partial sums -> atomicAdd into gsum[64]
__global__ void gsum_kernel(const float* __restrict__ H, float* __restrict__ gsum, int n) {
    int f = threadIdx.x;
    float acc = 0.f;
    for (int i = blockIdx.x; i < n; i += gridDim.x)
        acc += H[(size_t)i * HID + f];
    atomicAdd(&gsum[f], acc);
}

// per-sheet: gather+mean (folded-in sheet pooling), geo MLP, fusion, q head.
__global__ void tail_kernel(const float* __restrict__ H, const int* __restrict__ idx,
                            const float* __restrict__ sheet_feat,
                            const float* __restrict__ geoW1, const float* __restrict__ geob1,
                            const float* __restrict__ geoW2, const float* __restrict__ geob2,
                            const float* __restrict__ fusW,  const float* __restrict__ fusb,
                            const float* __restrict__ qW1,   const float* __restrict__ qb1,
                            const float* __restrict__ qW2,   const float* __restrict__ qb2,
                            const float* __restrict__ gsum, float inv_n,
                            float* __restrict__ out) {
    __shared__ float sf[FEAT], t1[HID], geo[HID], se[HID], fused[HID], g[HID];
    __shared__ float red[2];
    int s = blockIdx.x, j = threadIdx.x;

    // sheet mean pooling (was sheet_kernel)
    {
        const int* row = idx + s * SHEET_LEN;
        float acc = 0.f;
        #pragma unroll 4
        for (int r = 0; r < SHEET_LEN; r++) {
            int node = row[r];               // warp-uniform
            acc += H[(size_t)node * HID + j];
        }
        se[j] = acc * (1.0f / SHEET_LEN);
    }
    if (j < FEAT) sf[j] = sheet_feat[s * FEAT + j];
    g[j] = gsum[j] * inv_n;
    __syncthreads();

    float a = geob1[j];
    #pragma unroll
    for (int k = 0; k < FEAT; k++) a = fmaf(sf[k], geoW1[k * HID + j], a);
    t1[j] = fmaxf(a, 0.f);
    __syncthreads();

    a = geob2[j];
    #pragma unroll 8
    for (int k = 0; k < HID; k++) a = fmaf(t1[k], geoW2[k * HID + j], a);
    geo[j] = a;
    __syncthreads();

    a = fusb[j];
    #pragma unroll 8
    for (int k = 0; k < HID; k++) a = fmaf(se[k],  fusW[k * HID + j], a);
    #pragma unroll 8
    for (int k = 0; k < HID; k++) a = fmaf(geo[k], fusW[(HID + k) * HID + j], a);
    fused[j] = fmaxf(a, 0.f);
    __syncthreads();

    a = qb1[j];
    #pragma unroll 8
    for (int k = 0; k < HID; k++) a = fmaf(fused[k], qW1[k * HID + j], a);
    #pragma unroll 8
    for (int k = 0; k < HID; k++) a = fmaf(g[k],     qW1[(HID + k) * HID + j], a);
    float q = fmaxf(a, 0.f) * qW2[j];

    #pragma unroll
    for (int off = 16; off; off >>= 1) q += __shfl_down_sync(0xffffffffu, q, off);
    if ((j & 31) == 0) red[j >> 5] = q;
    __syncthreads();
    if (j == 0) out[s] = red[0] + red[1] + qb2[0];
}

// ---------------- launch ----------------

extern "C" void kernel_launch(void* const* d_in, const int* in_sizes, int n_in,
                              void* d_out, int out_size) {
    const float* x          = (const float*)d_in[0];
    const int*   ei         = (const int*)d_in[1];   // [2, E], int32
    const int*   sheet_idx  = (const int*)d_in[3];
    const float* sheet_feat = (const float*)d_in[4];
    const float* W1 = (const float*)d_in[5];  const float* b1 = (const float*)d_in[6];
    const float* W2 = (const float*)d_in[7];  const float* b2 = (const float*)d_in[8];
    const float* W3 = (const float*)d_in[9];  const float* b3 = (const float*)d_in[10];
    const float* gW1 = (const float*)d_in[11]; const float* gb1 = (const float*)d_in[12];
    const float* gW2 = (const float*)d_in[13]; const float* gb2 = (const float*)d_in[14];
    const float* fW  = (const float*)d_in[15]; const float* fb  = (const float*)d_in[16];
    const float* qW1 = (const float*)d_in[17]; const float* qb1 = (const float*)d_in[18];
    const float* qW2 = (const float*)d_in[19]; const float* qb2 = (const float*)d_in[20];
    float* out = (float*)d_out;

    const int* src = ei;
    const int* dst = ei + N_EDGES;

    float *hA, *hB, *dinv, *gsum;
    int *deg, *rowptr, *rowcur, *csrsrc, *part;
    cudaGetSymbolAddress((void**)&hA, d_hA);
    cudaGetSymbolAddress((void**)&hB, d_hB);
    cudaGetSymbolAddress((void**)&deg, d_deg);
    cudaGetSymbolAddress((void**)&dinv, d_dinv);
    cudaGetSymbolAddress((void**)&rowptr, d_rowptr);
    cudaGetSymbolAddress((void**)&rowcur, d_rowcur);
    cudaGetSymbolAddress((void**)&csrsrc, d_csrsrc);
    cudaGetSymbolAddress((void**)&part, d_part);
    cudaGetSymbolAddress((void**)&gsum, d_gsum);

    // --- CSR build ---
    zero_kernel<<<(N_NODES + 255) / 256, 256>>>(deg, gsum, N_NODES);
    deg_kernel<<<(N_EDGES + 255) / 256, 256>>>(dst, deg, N_EDGES);
    scan1_kernel<<<SCAN_GRID, SCAN_BLK>>>(deg, dinv, part, N_NODES);
    scan2_kernel<<<1, 128>>>(part, SCAN_GRID, rowptr + N_NODES);
    scan3_kernel<<<SCAN_GRID, SCAN_BLK>>>(deg, part, rowptr, rowcur, N_NODES);
    scatter_kernel<<<(N_EDGES + 255) / 256, 256>>>(src, dst, rowcur, csrsrc, N_EDGES);

    const int layer_grid = (N_NODES + NPB - 1) / NPB;   // 782

    // fused layers: relu(agg(H) @ W + b)  [agg-first via linearity]
    layer_kernel<FEAT><<<layer_grid, LAYER_THREADS>>>(x,  rowptr, csrsrc, dinv, W1, b1, hB, N_NODES);
    layer_kernel<HID> <<<layer_grid, LAYER_THREADS>>>(hB, rowptr, csrsrc, dinv, W2, b2, hA, N_NODES);
    layer_kernel<HID> <<<layer_grid, LAYER_THREADS>>>(hA, rowptr, csrsrc, dinv, W3, b3, hB, N_NODES);

    // pooling + tail
    gsum_kernel<<<256, HID>>>(hB, gsum, N_NODES);
    tail_kernel<<<N_SHEETS, HID>>>(hB, sheet_idx, sheet_feat,
                                   gW1, gb1, gW2, gb2, fW, fb, qW1, qb1, qW2, qb2,
                                   gsum, 1.0f / N_NODES, out);
}

// round 9
// speedup vs baseline: 1.6836x; 1.6836x over previous
#include <cuda_runtime.h>
#include <cuda_bf16.h>
#include <cuda_fp16.h>

#define N_NODES 50000
#define N_EDGES 800000
#define FEAT 10
#define HID 64
#define N_SHEETS 256
#define SHEET_LEN 128

#define SCAN_BLK 512
#define SCAN_GRID ((N_NODES + SCAN_BLK - 1) / SCAN_BLK)   // 98

// ---------------- scratch (static device globals; no allocation) ----------------
__device__ __align__(16) float d_hA[N_NODES * HID];   // fp16 gemm outputs live here (cast)
__device__ __align__(16) float d_hB[N_NODES * HID];   // fp32 agg outputs / gemm inputs
__device__ int   d_deg[N_NODES];
__device__ float d_dinv[N_NODES];
__device__ int   d_rowptr[N_NODES + 1];
__device__ int   d_rowcur[N_NODES];
__device__ int   d_csrsrc[N_EDGES];
__device__ float d_csrw[N_EDGES];
__device__ int   d_part[SCAN_GRID + 32];
__device__ float d_gsum[HID];

// ---------------- CSR build ----------------

__global__ void zero_kernel(int* deg, float* gsum, int n) {
    int i = blockIdx.x * blockDim.x + threadIdx.x;
    if (i < n) deg[i] = 0;
    if (i < HID) gsum[i] = 0.f;
}

__global__ void deg_kernel(const int* __restrict__ dst, int* __restrict__ deg, int nE) {
    int e = blockIdx.x * blockDim.x + threadIdx.x;
    if (e < nE) atomicAdd(&deg[dst[e]], 1);
}

// pass 1: per-block sums of deg, plus dinv (reads deg anyway)
__global__ void scan1_kernel(const int* __restrict__ deg, float* __restrict__ dinv,
                             int* __restrict__ partials, int n) {
    __shared__ int ws[SCAN_BLK / 32];
    int i = blockIdx.x * blockDim.x + threadIdx.x;
    int lane = threadIdx.x & 31, wrp = threadIdx.x >> 5;
    int v = (i < n) ? deg[i] : 0;
    if (i < n) dinv[i] = rsqrtf((float)v + 1.0f);
    int s = v;
    #pragma unroll
    for (int off = 16; off; off >>= 1) s += __shfl_down_sync(0xffffffffu, s, off);
    if (lane == 0) ws[wrp] = s;
    __syncthreads();
    if (wrp == 0) {
        int t = (lane < SCAN_BLK / 32) ? ws[lane] : 0;
        #pragma unroll
        for (int off = 16; off; off >>= 1) t += __shfl_down_sync(0xffffffffu, t, off);
        if (lane == 0) partials[blockIdx.x] = t;
    }
}

// pass 2: exclusive scan of the 98 block partials
__global__ void scan2_kernel(int* __restrict__ partials, int nb, int* __restrict__ total_dst) {
    __shared__ int ws[4];
    int t = threadIdx.x;
    int lane = t & 31, wrp = t >> 5;
    int v = (t < nb) ? partials[t] : 0;
    int x = v;
    #pragma unroll
    for (int off = 1; off < 32; off <<= 1) {
        int y = __shfl_up_sync(0xffffffffu, x, off);
        if (lane >= off) x += y;
    }
    if (lane == 31) ws[wrp] = x;
    __syncthreads();
    if (wrp == 0 && lane < 4) {
        int y = ws[lane];
        #pragma unroll
        for (int off = 1; off < 4; off <<= 1) {
            int z = __shfl_up_sync(0x0000000fu, y, off);
            if (lane >= off) y += z;
        }
        ws[lane] = y;
    }
    __syncthreads();
    int incl = x + (wrp > 0 ? ws[wrp - 1] : 0);
    if (t < nb) partials[t] = incl - v;
    if (t == 127) *total_dst = incl;
}

// pass 3: per-block rescan + offset -> rowptr/rowcur
__global__ void scan3_kernel(const int* __restrict__ deg, const int* __restrict__ partials,
                             int* __restrict__ row_ptr, int* __restrict__ row_cur, int n) {
    __shared__ int ws[SCAN_BLK / 32];
    int i = blockIdx.x * blockDim.x + threadIdx.x;
    int lane = threadIdx.x & 31, wrp = threadIdx.x >> 5;
    int v = (i < n) ? deg[i] : 0;
    int x = v;
    #pragma unroll
    for (int off = 1; off < 32; off <<= 1) {
        int y = __shfl_up_sync(0xffffffffu, x, off);
        if (lane >= off) x += y;
    }
    if (lane == 31) ws[wrp] = x;
    __syncthreads();
    if (wrp == 0) {
        int y = (lane < SCAN_BLK / 32) ? ws[lane] : 0;
        #pragma unroll
        for (int off = 1; off < 16; off <<= 1) {
            int z = __shfl_up_sync(0xffffffffu, y, off);
            if (lane >= off) y += z;
        }
        if (lane < SCAN_BLK / 32) ws[lane] = y;
    }
    __syncthreads();
    int excl = x - v + (wrp > 0 ? ws[wrp - 1] : 0) + partials[blockIdx.x];
    if (i < n) { row_ptr[i] = excl; row_cur[i] = excl; }
}

// scatter with fused edge weight: csrw = dinv[src] * dinv[dst]
__global__ void scatter_kernel(const int* __restrict__ src, const int* __restrict__ dst,
                               const float* __restrict__ dinv,
                               int* __restrict__ rowcur, int* __restrict__ csrsrc,
                               float* __restrict__ csrw, int nE) {
    int e = blockIdx.x * blockDim.x + threadIdx.x;
    if (e >= nE) return;
    int d = dst[e];
    int s = src[e];
    int p = atomicAdd(&rowcur[d], 1);
    csrsrc[p] = s;
    csrw[p] = dinv[s] * dinv[d];
}

// ---------------- layer kernels ----------------

// layer-1 pre-agg on raw features (A·X), 10-wide.  out = sum_e w_e*x_src + di^2*x_i
__global__ void aggx_kernel(const float* __restrict__ X, const int* __restrict__ row_ptr,
                            const int* __restrict__ csrsrc, const float* __restrict__ csrw,
                            const float* __restrict__ dinv,
                            float* __restrict__ out, int n) {
    int warp = (blockIdx.x * blockDim.x + threadIdx.x) >> 5;
    int lane = threadIdx.x & 31;
    if (warp >= n) return;
    int beg = row_ptr[warp];
    int end = row_ptr[warp + 1];
    float acc = 0.f;
    for (int e = beg; e < end; e++) {
        int s   = csrsrc[e];               // warp-uniform, independent loads
        float w = csrw[e];                 // warp-uniform
        if (lane < FEAT)
            acc = fmaf(w, X[(size_t)s * FEAT + lane], acc);
    }
    if (lane < FEAT) {
        float di = dinv[warp];
        float xv = X[(size_t)warp * FEAT + lane];
        out[(size_t)warp * FEAT + lane] = fmaf(di * di, xv, acc);
    }
}

// fused gemm1+gemm2:  G = relu(T0 @ W1 + b1) @ W2   (T0 10-wide), output fp16
__global__ void __launch_bounds__(128)
gemm12_kernel(const float* __restrict__ T0, const float* __restrict__ W1,
              const float* __restrict__ b1, const float* __restrict__ W2,
              __half* __restrict__ Hout, int n) {
    __shared__ __align__(16) float W1sm[FEAT * HID];
    __shared__ __align__(16) float W2sm[HID * HID];
    __shared__ float b1sm[HID];
    int tid = threadIdx.x;
    for (int i = tid; i < FEAT * HID; i += 128) W1sm[i] = W1[i];
    for (int i = tid; i < HID * HID; i += 128) W2sm[i] = W2[i];
    if (tid < HID) b1sm[tid] = b1[tid];
    __syncthreads();
    int node = blockIdx.x * 128 + tid;
    if (node >= n) return;

    float xv[FEAT];
    {
        const float2* xr = (const float2*)(T0 + (size_t)node * FEAT);
        #pragma unroll
        for (int i = 0; i < FEAT / 2; i++) {
            float2 v = xr[i];
            xv[2 * i] = v.x; xv[2 * i + 1] = v.y;
        }
    }
    float h[HID];
    #pragma unroll
    for (int j = 0; j < HID; j++) h[j] = b1sm[j];
    #pragma unroll
    for (int k = 0; k < FEAT; k++) {
        const float4* wr = (const float4*)&W1sm[k * HID];
        #pragma unroll
        for (int j = 0; j < 16; j++) {
            float4 w = wr[j];
            h[4*j+0] = fmaf(xv[k], w.x, h[4*j+0]);
            h[4*j+1] = fmaf(xv[k], w.y, h[4*j+1]);
            h[4*j+2] = fmaf(xv[k], w.z, h[4*j+2]);
            h[4*j+3] = fmaf(xv[k], w.w, h[4*j+3]);
        }
    }
    #pragma unroll
    for (int j = 0; j < HID; j++) h[j] = fmaxf(h[j], 0.f);

    float g[HID];
    #pragma unroll
    for (int j = 0; j < HID; j++) g[j] = 0.f;
    #pragma unroll
    for (int k = 0; k < HID; k++) {
        float hv = h[k];
        const float4* wr = (const float4*)&W2sm[k * HID];
        #pragma unroll
        for (int j = 0; j < 16; j++) {
            float4 w = wr[j];
            g[4*j+0] = fmaf(hv, w.x, g[4*j+0]);
            g[4*j+1] = fmaf(hv, w.y, g[4*j+1]);
            g[4*j+2] = fmaf(hv, w.z, g[4*j+2]);
            g[4*j+3] = fmaf(hv, w.w, g[4*j+3]);
        }
    }
    __half2 hh[HID / 2];
    #pragma unroll
    for (int i = 0; i < HID / 2; i++)
        hh[i] = __floats2half2_rn(g[2 * i], g[2 * i + 1]);
    uint4* orow = (uint4*)(Hout + (size_t)node * HID);
    const uint4* hr = (const uint4*)hh;
    #pragma unroll
    for (int i = 0; i < 8; i++) orow[i] = hr[i];
}

// gemm3:  G = X @ W3  (64-wide fp32 in), output fp16, no bias/relu (done in agg)
__global__ void __launch_bounds__(128)
gemm_kernel(const float* __restrict__ X, const float* __restrict__ W,
            __half* __restrict__ Hout, int n) {
    __shared__ __align__(16) float Wsm[HID * HID];
    int tid = threadIdx.x;
    for (int i = tid; i < HID * HID; i += 128) Wsm[i] = W[i];
    __syncthreads();
    int node = blockIdx.x * 128 + tid;
    if (node >= n) return;

    float xv[HID];
    {
        const float4* xr = (const float4*)(X + (size_t)node * HID);
        #pragma unroll
        for (int i = 0; i < 16; i++) {
            float4 v = xr[i];
            xv[4*i] = v.x; xv[4*i+1] = v.y; xv[4*i+2] = v.z; xv[4*i+3] = v.w;
        }
    }
    float g[HID];
    #pragma unroll
    for (int j = 0; j < HID; j++) g[j] = 0.f;
    #pragma unroll
    for (int k = 0; k < HID; k++) {
        float hv = xv[k];
        const float4* wr = (const float4*)&Wsm[k * HID];
        #pragma unroll
        for (int j = 0; j < 16; j++) {
            float4 w = wr[j];
            g[4*j+0] = fmaf(hv, w.x, g[4*j+0]);
            g[4*j+1] = fmaf(hv, w.y, g[4*j+1]);
            g[4*j+2] = fmaf(hv, w.z, g[4*j+2]);
            g[4*j+3] = fmaf(hv, w.w, g[4*j+3]);
        }
    }
    __half2 hh[HID / 2];
    #pragma unroll
    for (int i = 0; i < HID / 2; i++)
        hh[i] = __floats2half2_rn(g[2 * i], g[2 * i + 1]);
    uint4* orow = (uint4*)(Hout + (size_t)node * HID);
    const uint4* hr = (const uint4*)hh;
    #pragma unroll
    for (int i = 0; i < 8; i++) orow[i] = hr[i];
}

// agg on fp16 rows: out = relu(sum_e w_e*h_src + di^2*h_i + b).  Warp per node.
__global__ void agg16_kernel(const __half2* __restrict__ H2, const int* __restrict__ row_ptr,
                             const int* __restrict__ csrsrc, const float* __restrict__ csrw,
                             const float* __restrict__ dinv, const float* __restrict__ b,
                             float* __restrict__ out, int n) {
    int warp = (blockIdx.x * blockDim.x + threadIdx.x) >> 5;
    int lane = threadIdx.x & 31;
    if (warp >= n) return;
    int beg = row_ptr[warp];
    int end = row_ptr[warp + 1];
    float a0 = 0.f, a1 = 0.f;
    for (int e = beg; e < end; e++) {
        int s   = csrsrc[e];               // warp-uniform
        float w = csrw[e];                 // warp-uniform, independent of s
        float2 f = __half22float2(H2[(size_t)s * 32 + lane]);   // 128B coalesced
        a0 = fmaf(w, f.x, a0);
        a1 = fmaf(w, f.y, a1);
    }
    float di = dinv[warp];
    float d2 = di * di;
    float2 fs = __half22float2(H2[(size_t)warp * 32 + lane]);
    float2 bb = ((const float2*)b)[lane];
    a0 = fmaf(d2, fs.x, a0) + bb.x;
    a1 = fmaf(d2, fs.y, a1) + bb.y;
    ((float2*)out)[(size_t)warp * 32 + lane] = make_float2(fmaxf(a0, 0.f), fmaxf(a1, 0.f));
}

// ---------------- pooling + tail ----------------

__global__ void gsum_kernel(const float* __restrict__ H, float* __restrict__ gsum, int n) {
    int f = threadIdx.x;
    float acc = 0.f;
    for (int i = blockIdx.x; i < n; i += gridDim.x)
        acc += H[(size_t)i * HID + f];
    atomicAdd(&gsum[f], acc);
}

// per-sheet: gather+mean, geo MLP, fusion, q head.  Block (64 threads) per sheet.
__global__ void tail_kernel(const float* __restrict__ H, const int* __restrict__ idx,
                            const float* __restrict__ sheet_feat,
                            const float* __restrict__ geoW1, const float* __restrict__ geob1,
                            const float* __restrict__ geoW2, const float* __restrict__ geob2,
                            const float* __restrict__ fusW,  const float* __restrict__ fusb,
                            const float* __restrict__ qW1,   const float* __restrict__ qb1,
                            const float* __restrict__ qW2,   const float* __restrict__ qb2,
                            const float* __restrict__ gsum, float inv_n,
                            float* __restrict__ out) {
    __shared__ float sf[FEAT], t1[HID], geo[HID], se[HID], fused[HID], g[HID];
    __shared__ float red[2];
    int s = blockIdx.x, j = threadIdx.x;

    {
        const int* row = idx + s * SHEET_LEN;
        float acc = 0.f;
        #pragma unroll 4
        for (int r = 0; r < SHEET_LEN; r++) {
            int node = row[r];               // warp-uniform
            acc += H[(size_t)node * HID + j];
        }
        se[j] = acc * (1.0f / SHEET_LEN);
    }
    if (j < FEAT) sf[j] = sheet_feat[s * FEAT + j];
    g[j] = gsum[j] * inv_n;
    __syncthreads();

    float a = geob1[j];
    #pragma unroll
    for (int k = 0; k < FEAT; k++) a = fmaf(sf[k], geoW1[k * HID + j], a);
    t1[j] = fmaxf(a, 0.f);
    __syncthreads();

    a = geob2[j];
    #pragma unroll 8
    for (int k = 0; k < HID; k++) a = fmaf(t1[k], geoW2[k * HID + j], a);
    geo[j] = a;
    __syncthreads();

    a = fusb[j];
    #pragma unroll 8
    for (int k = 0; k < HID; k++) a = fmaf(se[k],  fusW[k * HID + j], a);
    #pragma unroll 8
    for (int k = 0; k < HID; k++) a = fmaf(geo[k], fusW[(HID + k) * HID + j], a);
    fused[j] = fmaxf(a, 0.f);
    __syncthreads();

    a = qb1[j];
    #pragma unroll 8
    for (int k = 0; k < HID; k++) a = fmaf(fused[k], qW1[k * HID + j], a);
    #pragma unroll 8
    for (int k = 0; k < HID; k++) a = fmaf(g[k],     qW1[(HID + k) * HID + j], a);
    float q = fmaxf(a, 0.f) * qW2[j];

    #pragma unroll
    for (int off = 16; off; off >>= 1) q += __shfl_down_sync(0xffffffffu, q, off);
    if ((j & 31) == 0) red[j >> 5] = q;
    __syncthreads();
    if (j == 0) out[s] = red[0] + red[1] + qb2[0];
}

// ---------------- launch ----------------

extern "C" void kernel_launch(void* const* d_in, const int* in_sizes, int n_in,
                              void* d_out, int out_size) {
    const float* x          = (const float*)d_in[0];
    const int*   ei         = (const int*)d_in[1];   // [2, E], int32
    const int*   sheet_idx  = (const int*)d_in[3];
    const float* sheet_feat = (const float*)d_in[4];
    const float* W1 = (const float*)d_in[5];  const float* b1 = (const float*)d_in[6];
    const float* W2 = (const float*)d_in[7];  const float* b2 = (const float*)d_in[8];
    const float* W3 = (const float*)d_in[9];  const float* b3 = (const float*)d_in[10];
    const float* gW1 = (const float*)d_in[11]; const float* gb1 = (const float*)d_in[12];
    const float* gW2 = (const float*)d_in[13]; const float* gb2 = (const float*)d_in[14];
    const float* fW  = (const float*)d_in[15]; const float* fb  = (const float*)d_in[16];
    const float* qW1 = (const float*)d_in[17]; const float* qb1 = (const float*)d_in[18];
    const float* qW2 = (const float*)d_in[19]; const float* qb2 = (const float*)d_in[20];
    float* out = (float*)d_out;

    const int* src = ei;
    const int* dst = ei + N_EDGES;

    float *hA, *hB, *dinv, *gsum, *csrw;
    int *deg, *rowptr, *rowcur, *csrsrc, *part;
    cudaGetSymbolAddress((void**)&hA, d_hA);
    cudaGetSymbolAddress((void**)&hB, d_hB);
    cudaGetSymbolAddress((void**)&deg, d_deg);
    cudaGetSymbolAddress((void**)&dinv, d_dinv);
    cudaGetSymbolAddress((void**)&rowptr, d_rowptr);
    cudaGetSymbolAddress((void**)&rowcur, d_rowcur);
    cudaGetSymbolAddress((void**)&csrsrc, d_csrsrc);
    cudaGetSymbolAddress((void**)&csrw, d_csrw);
    cudaGetSymbolAddress((void**)&part, d_part);
    cudaGetSymbolAddress((void**)&gsum, d_gsum);

    __half* hA16 = (__half*)hA;
    __half2* hA2 = (__half2*)hA;

    // --- CSR build ---
    zero_kernel<<<(N_NODES + 255) / 256, 256>>>(deg, gsum, N_NODES);
    deg_kernel<<<(N_EDGES + 255) / 256, 256>>>(dst, deg, N_EDGES);
    scan1_kernel<<<SCAN_GRID, SCAN_BLK>>>(deg, dinv, part, N_NODES);
    scan2_kernel<<<1, 128>>>(part, SCAN_GRID, rowptr + N_NODES);
    scan3_kernel<<<SCAN_GRID, SCAN_BLK>>>(deg, part, rowptr, rowcur, N_NODES);
    scatter_kernel<<<(N_EDGES + 255) / 256, 256>>>(src, dst, dinv, rowcur, csrsrc, csrw, N_EDGES);

    const int gemm_grid = (N_NODES + 127) / 128;
    const int agg_grid  = (N_NODES * 32 + 255) / 256;

    // layer 1+2 front half:  t0 = agg(x);  g2 = relu(t0·W1+b1)·W2  (fp16 out)
    aggx_kernel<<<agg_grid, 256>>>(x, rowptr, csrsrc, csrw, dinv, hB, N_NODES);
    gemm12_kernel<<<gemm_grid, 128>>>(hB, W1, b1, W2, hA16, N_NODES);
    // layer 2 aggregation: h2 = relu(agg(g2)+b2)   (fp32 out)
    agg16_kernel<<<agg_grid, 256>>>(hA2, rowptr, csrsrc, csrw, dinv, b2, hB, N_NODES);
    // layer 3: g3 = h2·W3 (fp16), h3 = relu(agg(g3)+b3) (fp32)
    gemm_kernel<<<gemm_grid, 128>>>(hB, W3, hA16, N_NODES);
    agg16_kernel<<<agg_grid, 256>>>(hA2, rowptr, csrsrc, csrw, dinv, b3, hB, N_NODES);

    // pooling + tail
    gsum_kernel<<<256, HID>>>(hB, gsum, N_NODES);
    tail_kernel<<<N_SHEETS, HID>>>(hB, sheet_idx, sheet_feat,
                                   gW1, gb1, gW2, gb2, fW, fb, qW1, qb1, qW2, qb2,
                                   gsum, 1.0f / N_NODES, out);
}